// round 7
// baseline (speedup 1.0000x reference)
#include <cuda_runtime.h>
#include <math.h>

#define NMAX 16384
#define KNN  11          // neighbors kept (K=12 graph minus self)
#define G    48          // grid cells per dim
#define NC   (G * G * G) // 110592 cells
#define CCAP 20          // points per cell before overflow
#define XMIN (-4.8f)
#define H    0.2f
#define INVH 5.0f
#define RADCAP 1.19f     // max search radius (6 cells per side)
#define RTPB 256
#define RGRID 512

// Static device scratch (no allocations allowed).
__device__ float4 g_pk[NMAX];           // x,y,z,|p|^2 (for repair + gather)
__device__ float  g_seed[NMAX];         // capped seed threshold (d^2 units)
__device__ int    g_cnt[NC];            // per-cell point count
__device__ float4 g_cellp[NC * CCAP];   // per-cell points: x,y,z,bitcast(idx)
__device__ int    g_ovf_cnt;
__device__ float4 g_ovf[1024];          // overflow points (rarely used)
__device__ int    g_fail_cnt;
__device__ int    g_fail[NMAX];

__global__ void zero_kernel() {
    int i = blockIdx.x * blockDim.x + threadIdx.x;
    if (i < NC) g_cnt[i] = 0;
    if (i == 0) { g_ovf_cnt = 0; g_fail_cnt = 0; }
}

__global__ void bin_kernel(const float* __restrict__ p, int n) {
    int i = blockIdx.x * blockDim.x + threadIdx.x;
    if (i >= n) return;
    float x = p[3 * i + 0];
    float y = p[3 * i + 1];
    float z = p[3 * i + 2];
    float q2 = x * x + y * y + z * z;
    g_pk[i] = make_float4(x, y, z, q2);

    // Analytic 11-NN radius from local Gaussian density:
    // lambda = n*(2pi)^{-3/2}*exp(-q2/2);  r^3 = 33/(4pi*lambda)
    float lam = (float)n * 0.063493636f * __expf(-0.5f * q2);
    float f = 2.6260608f / lam;
    float r2 = cbrtf(f * f);                  // expected r11^2
    float fac = 2.0f + 0.15f * q2;            // tail-ramped safety
    float seed = fminf(fac * r2, RADCAP * RADCAP);
    g_seed[i] = seed;

    int ix = min(max((int)floorf((x - XMIN) * INVH), 0), G - 1);
    int iy = min(max((int)floorf((y - XMIN) * INVH), 0), G - 1);
    int iz = min(max((int)floorf((z - XMIN) * INVH), 0), G - 1);
    int cell = (iz * G + iy) * G + ix;

    int slot = atomicAdd(&g_cnt[cell], 1);
    float4 rec = make_float4(x, y, z, __int_as_float(i));
    if (slot < CCAP) {
        g_cellp[cell * CCAP + slot] = rec;
    } else {
        int o = atomicAdd(&g_ovf_cnt, 1);
        if (o < 1024) g_ovf[o] = rec;
    }
}

__device__ __forceinline__ void ins(float d, int j, float dist[KNN], int idxk[KNN]) {
    float dd = d; int jj = j;
#pragma unroll
    for (int k = 0; k < KNN; k++) {
        if (dd < dist[k]) {
            float td = dist[k]; int tj = idxk[k];
            dist[k] = dd; idxk[k] = jj;
            dd = td;      jj = tj;
        }
    }
}

// Grid query: thread per query. Scans all cells intersecting the seed ball;
// exact top-11 among points with d^2 < seed. If fewer than 11 found, the true
// 11-NN may lie outside the ball -> exact repair. Otherwise exact by the
// ball-covering argument (unscanned points have d^2 >= seed > dist[10]).
__global__ __launch_bounds__(128) void query_kernel(
    const float* __restrict__ W,
    const float* __restrict__ Bb,
    float* __restrict__ out,
    int n)
{
    int qi = blockIdx.x * 128 + threadIdx.x;
    if (qi >= n) return;

    float4 q = g_pk[qi];
    float qx = q.x, qy = q.y, qz = q.z;
    float seed = g_seed[qi];
    float rad = sqrtf(seed);

    int x0 = min(max((int)floorf((qx - rad - XMIN) * INVH), 0), G - 1);
    int x1 = min(max((int)floorf((qx + rad - XMIN) * INVH), 0), G - 1);
    int y0 = min(max((int)floorf((qy - rad - XMIN) * INVH), 0), G - 1);
    int y1 = min(max((int)floorf((qy + rad - XMIN) * INVH), 0), G - 1);
    int z0 = min(max((int)floorf((qz - rad - XMIN) * INVH), 0), G - 1);
    int z1 = min(max((int)floorf((qz + rad - XMIN) * INVH), 0), G - 1);

    float dist[KNN]; int idxk[KNN];
#pragma unroll
    for (int k = 0; k < KNN; k++) { dist[k] = seed; idxk[k] = -1; }

    for (int iz = z0; iz <= z1; iz++) {
        for (int iy = y0; iy <= y1; iy++) {
            int rowc = (iz * G + iy) * G;
            for (int ix = x0; ix <= x1; ix++) {
                int cell = rowc + ix;
                int cnt = min(g_cnt[cell], CCAP);
                const float4* base = g_cellp + cell * CCAP;
                for (int k = 0; k < cnt; k++) {
                    float4 c = base[k];
                    float dx = qx - c.x;
                    float dy = qy - c.y;
                    float dz = qz - c.z;
                    float d = fmaf(dz, dz, fmaf(dy, dy, dx * dx));
                    int j = __float_as_int(c.w);
                    if (d < dist[KNN - 1] && j != qi) ins(d, j, dist, idxk);
                }
            }
        }
    }

    // Overflow points (points that didn't fit their cell) — scan exactly.
    int no = min(g_ovf_cnt, 1024);
    for (int o = 0; o < no; o++) {
        float4 c = g_ovf[o];
        float dx = qx - c.x;
        float dy = qy - c.y;
        float dz = qz - c.z;
        float d = fmaf(dz, dz, fmaf(dy, dy, dx * dx));
        int j = __float_as_int(c.w);
        if (d < dist[KNN - 1] && j != qi) ins(d, j, dist, idxk);
    }

    if (idxk[KNN - 1] < 0 || g_ovf_cnt > 1024) {
        int slot = atomicAdd(&g_fail_cnt, 1);
        g_fail[slot] = qi;
        return;
    }

    float w0 = W[0], w1 = W[1], w2 = W[2];
    float Ssum = 0.0f;
#pragma unroll
    for (int k = 0; k < KNN; k++) {
        float4 c = g_pk[idxk[k]];
        Ssum += fabsf(qx - c.x) * w0 + fabsf(qy - c.y) * w1 + fabsf(qz - c.z) * w2;
    }

    float xw0 = qx * w0 + qy * w1 + qz * w2;
    const float inv_s2 = 0.7071067811865475f;
    const float c0f = (1.0f + (float)KNN * inv_s2) / 12.0f; // (1 + 11/sqrt2)/12
    const float c1f = 1.0f / 24.0f;                          // 0.5/12
    out[qi] = fmaf(c0f, xw0, fmaf(c1f, Ssum, Bb[0]));
}

// Exact repair: block-per-failed-query brute force with tournament merge.
__global__ __launch_bounds__(RTPB) void repair_kernel(
    const float* __restrict__ W,
    const float* __restrict__ Bb,
    float* __restrict__ out,
    int n)
{
    __shared__ float sd[RTPB * KNN];
    __shared__ int   si[RTPB * KNN];

    int tid = threadIdx.x;
    int nf = g_fail_cnt;

    for (int f = blockIdx.x; f < nf; f += gridDim.x) {
        int qi = g_fail[f];
        float4 q = g_pk[qi];
        float qx = q.x, qy = q.y, qz = q.z;

        float dist[KNN]; int idxk[KNN];
#pragma unroll
        for (int k = 0; k < KNN; k++) { dist[k] = 3.0e38f; idxk[k] = -1; }

        for (int j = tid; j < n; j += RTPB) {
            float4 c = g_pk[j];
            float dx = qx - c.x;
            float dy = qy - c.y;
            float dz = qz - c.z;
            float d = fmaf(dz, dz, fmaf(dy, dy, dx * dx));
            if (d < dist[KNN - 1] && j != qi) ins(d, j, dist, idxk);
        }
#pragma unroll
        for (int k = 0; k < KNN; k++) {
            sd[tid * KNN + k] = dist[k];
            si[tid * KNN + k] = idxk[k];
        }
        __syncthreads();

        // Tournament merge: log2(RTPB) levels, early break on sorted lists.
        for (int stride = RTPB / 2; stride >= 1; stride >>= 1) {
            if (tid < stride) {
                int prow = (tid + stride) * KNN;
#pragma unroll
                for (int k = 0; k < KNN; k++) {
                    float d = sd[prow + k];
                    if (d >= dist[KNN - 1]) break;
                    int j = si[prow + k];
                    if (j < 0) break;
                    ins(d, j, dist, idxk);
                }
            }
            __syncthreads();
            if (tid < stride) {
#pragma unroll
                for (int k = 0; k < KNN; k++) {
                    sd[tid * KNN + k] = dist[k];
                    si[tid * KNN + k] = idxk[k];
                }
            }
            __syncthreads();
        }

        if (tid == 0) {
            float w0 = W[0], w1 = W[1], w2 = W[2];
            float Ssum = 0.0f;
#pragma unroll
            for (int k = 0; k < KNN; k++) {
                float4 c = g_pk[idxk[k]];
                Ssum += fabsf(qx - c.x) * w0 + fabsf(qy - c.y) * w1
                      + fabsf(qz - c.z) * w2;
            }
            float xw0 = qx * w0 + qy * w1 + qz * w2;
            const float inv_s2 = 0.7071067811865475f;
            const float c0f = (1.0f + (float)KNN * inv_s2) / 12.0f;
            const float c1f = 1.0f / 24.0f;
            out[qi] = fmaf(c0f, xw0, fmaf(c1f, Ssum, Bb[0]));
        }
        __syncthreads();
    }
}

extern "C" void kernel_launch(void* const* d_in, const int* in_sizes, int n_in,
                              void* d_out, int out_size) {
    const float* p = (const float*)d_in[0];   // [2*8192*3] fp32
    const float* W = (const float*)d_in[1];   // [3]
    const float* b = (const float*)d_in[2];   // [1]
    float* out = (float*)d_out;               // [n,1] fp32

    int n = in_sizes[0] / 3;                  // 16384

    zero_kernel<<<(NC + 255) / 256, 256>>>();
    bin_kernel<<<(n + 255) / 256, 256>>>(p, n);
    query_kernel<<<(n + 127) / 128, 128>>>(W, b, out, n);
    repair_kernel<<<RGRID, RTPB>>>(W, b, out, n);
}